// round 5
// baseline (speedup 1.0000x reference)
#include <cuda_runtime.h>
#include <cstdint>

// x: [64, 3, 512, 512] float32
// keep_mask: [64, 32, 32] -> widened to 32-bit words (nonzero == keep)
// out = x * upsample16(keep_mask)
//
// One thread = one patch-row segment (16 floats = 64B). Warp = one full
// (b,c,h) row (512 floats, 32 patches, 32 coalesced mask words). Masked
// patches: skip the read entirely (predicated LDG -> sectors elided),
// write zeros.

static constexpr int B = 64;
static constexpr int C = 3;
static constexpr int H = 512;
static constexpr int W = 512;
static constexpr long long N   = (long long)B * C * H * W;  // 50,331,648
static constexpr long long N16 = N / 16;                    // 3,145,728 segments

__global__ void __launch_bounds__(256) patchmask_kernel(
    const float4* __restrict__ x4,
    const uint32_t* __restrict__ keep,
    float4* __restrict__ out4)
{
    long long i = (long long)blockIdx.x * blockDim.x + threadIdx.x;
    if (i >= N16) return;

    // segment index: 32 segments per row (W/16), 512 rows per (b,c) image
    int pw = (int)(i & 31);              // patch col 0..31
    int h  = (int)((i >> 5) & (H - 1));  // pixel row 0..511
    int bc = (int)(i >> 14);             // b*C + c
    int b  = bc / C;

    int midx = b * 1024 + ((h >> 4) << 5) + pw;
    uint32_t m = __ldg(keep + midx);

    float4 v0 = make_float4(0.f, 0.f, 0.f, 0.f);
    float4 v1 = v0, v2 = v0, v3 = v0;

    long long j = i << 2;                // float4 index (4 per segment)
    if (m != 0u) {
        v0 = x4[j];
        v1 = x4[j + 1];
        v2 = x4[j + 2];
        v3 = x4[j + 3];
    }
    out4[j]     = v0;
    out4[j + 1] = v1;
    out4[j + 2] = v2;
    out4[j + 3] = v3;
}

extern "C" void kernel_launch(void* const* d_in, const int* in_sizes, int n_in,
                              void* d_out, int out_size)
{
    const float4*   x4   = (const float4*)d_in[0];
    const uint32_t* keep = (const uint32_t*)d_in[1];
    float4*         out4 = (float4*)d_out;

    const int threads = 256;
    const long long blocks = (N16 + threads - 1) / threads;  // 12288
    patchmask_kernel<<<(unsigned)blocks, threads>>>(x4, keep, out4);
}

// round 6
// speedup vs baseline: 1.1224x; 1.1224x over previous
#include <cuda_runtime.h>
#include <cstdint>

// x: [64, 3, 512, 512] float32
// keep_mask: [64, 32, 32] -> widened to 32-bit words (nonzero == keep)
// out = x * upsample16(keep_mask)
//
// R4 shape (best): 32B/thread, one mask word per thread, predicated read
// elision for masked patches. R6 adds: streaming cache hints (__ldcs/__stcs,
// zero-reuse stream), branchless predication, 512-thread blocks.

static constexpr int B = 64;
static constexpr int C = 3;
static constexpr int H = 512;
static constexpr int W = 512;
static constexpr long long N  = (long long)B * C * H * W;  // 50,331,648 floats
static constexpr long long N8 = N / 8;                     // 6,291,456 groups of 8

__global__ void __launch_bounds__(512) patchmask_kernel(
    const float4* __restrict__ x4,
    const uint32_t* __restrict__ keep,
    float4* __restrict__ out4)
{
    long long i = (long long)blockIdx.x * blockDim.x + threadIdx.x;
    if (i >= N8) return;

    long long base = i << 3;               // float index of first of 8 elems
    int w  = (int)(base & (W - 1));        // W = 512
    int h  = (int)((base >> 9) & (H - 1)); // H = 512
    int bc = (int)(base >> 18);            // b*C + c
    int b  = bc / C;                       // C = 3

    int midx = b * 1024 + ((h >> 4) << 5) + (w >> 4);
    bool m = __ldg(keep + midx) != 0u;

    const float4 z = make_float4(0.f, 0.f, 0.f, 0.f);
    long long j = i << 1;                  // float4 index

    // Branchless: ptxas emits predicated @p LDG.128 (sectors elided when !p).
    float4 v0 = m ? __ldcs(x4 + j)     : z;
    float4 v1 = m ? __ldcs(x4 + j + 1) : z;

    __stcs(out4 + j,     v0);
    __stcs(out4 + j + 1, v1);
}

extern "C" void kernel_launch(void* const* d_in, const int* in_sizes, int n_in,
                              void* d_out, int out_size)
{
    const float4*   x4   = (const float4*)d_in[0];
    const uint32_t* keep = (const uint32_t*)d_in[1];
    float4*         out4 = (float4*)d_out;

    const int threads = 512;
    const long long blocks = (N8 + threads - 1) / threads;  // 12288
    patchmask_kernel<<<(unsigned)blocks, threads>>>(x4, keep, out4);
}